// round 14
// baseline (speedup 1.0000x reference)
#include <cuda_runtime.h>
#include <cuda_fp16.h>
#include <cstdint>

#define B_     4
#define L_     256
#define NNODE  1024
#define DNODE  256
#define DPAIR  128
#define NE     65536
#define M0_    32
#define DIRR   56
#define WNUM_  1664

#define PW0   0.15811388300841897f
#define PW1   0.25f
#define S3C   0.5773502691896258f
#define F121  0.5477225575051661f

// device scratch (no allocations allowed)
__device__ float g_feats[NNODE * DIRR];
__device__ float g_sums [NNODE * DIRR];
__device__ float g_cnt  [NNODE];
// fp16 weights: fc1 plain; fc2 26-chunk 64-col permuted layout, pitch 72
__device__ uint4 g_w1[2176];     // 128 x 136 fp16 = 34,816 B
__device__ uint4 g_w2[29952];    // 26 x 128 x 72 fp16 = 479,232 B

// ---------------- plain-PTX helpers (sm_80-level, safe on sm_103) ----------
__device__ __forceinline__ uint32_t smem_u32(const void* p) {
    uint32_t a;
    asm("{ .reg .u64 t; cvta.to.shared.u64 t, %1; cvt.u32.u64 %0, t; }"
        : "=r"(a) : "l"(p));
    return a;
}
__device__ __forceinline__ void ldsm_x4(uint32_t* r, uint32_t addr) {
    asm volatile("ldmatrix.sync.aligned.m8n8.x4.shared.b16 {%0,%1,%2,%3}, [%4];"
        : "=r"(r[0]), "=r"(r[1]), "=r"(r[2]), "=r"(r[3]) : "r"(addr));
}
__device__ __forceinline__ void ldsm_x4t(uint32_t* r, uint32_t addr) {
    asm volatile("ldmatrix.sync.aligned.m8n8.x4.trans.shared.b16 {%0,%1,%2,%3}, [%4];"
        : "=r"(r[0]), "=r"(r[1]), "=r"(r[2]), "=r"(r[3]) : "r"(addr));
}
__device__ __forceinline__ void mma_f16(float* d, const uint32_t* a,
                                        uint32_t b0, uint32_t b1) {
    asm volatile("mma.sync.aligned.m16n8k16.row.col.f32.f16.f16.f32 "
        "{%0,%1,%2,%3}, {%4,%5,%6,%7}, {%8,%9}, {%0,%1,%2,%3};"
        : "+f"(d[0]), "+f"(d[1]), "+f"(d[2]), "+f"(d[3])
        : "r"(a[0]), "r"(a[1]), "r"(a[2]), "r"(a[3]), "r"(b0), "r"(b1));
}
__device__ __forceinline__ void cpasync16(uint32_t s, const void* g) {
    asm volatile("cp.async.cg.shared.global [%0], [%1], 16;" :: "r"(s), "l"(g));
}
#define CP_COMMIT() asm volatile("cp.async.commit_group;" ::: "memory")
#define CP_WAIT(N)  asm volatile("cp.async.wait_group %0;" :: "n"(N) : "memory")

// smem layout (bytes) -- 64 edges per CTA, 2 CTAs per SM
#define CHUNK_B  18432    // fc2 chunk: 128 rows x 72 fp16 (pitch 144)
#define SM_W     0        // single slot: fc1w halves, then fc2 chunks
#define SM_HHI   18432    // 64 x 136 fp16, pitch 272
#define SM_XLO   35840    // x-lo for fc1 (pitch 272); later F staging 64x64 f32
#define SM_A     53248    // x f32 staging 64x128; then A coeffs 64x185 f32
#define SM_F2B   100608   // 1664 f32
#define SM_F1B   107264   // 128 f32
#define SM_TOTAL 107776

#define THREADS  256
#define APITCH   185

// ---------------------------------------------------------------------------
__global__ void prep_zero_kernel() {
    int i = blockIdx.x * 1024 + threadIdx.x;
    if (i < NNODE * DIRR) g_sums[i] = 0.f;
    else if (i < NNODE * DIRR + NNODE) g_cnt[i - NNODE * DIRR] = 0.f;
}

__global__ __launch_bounds__(256) void prep_proj_kernel(
        const float* __restrict__ node, const float* __restrict__ w,
        const float* __restrict__ b,    const float* __restrict__ l1) {
    __shared__ float sw[DNODE * M0_];
    __shared__ float sx[16 * DNODE];
    int tid = threadIdx.x, n0 = blockIdx.x * 16;
    for (int i = tid; i < DNODE * M0_; i += 256) sw[i] = w[i];
    for (int i = tid; i < 16 * DNODE; i += 256) sx[i] = node[n0 * DNODE + i];
    __syncthreads();
    int warp = tid >> 5, lane = tid & 31;
    for (int r = 0; r < 2; ++r) {
        int nl = warp * 2 + r;
        float acc = b[lane];
        const float* x = sx + nl * DNODE;
#pragma unroll 8
        for (int k = 0; k < DNODE; ++k) acc += x[k] * sw[k * M0_ + lane];
        g_feats[(n0 + nl) * DIRR + lane] = acc;
    }
    for (int i = tid; i < 16 * 24; i += 256) {
        int nl = i / 24, m = i - nl * 24;
        g_feats[(n0 + nl) * DIRR + M0_ + m] = l1[(n0 + nl) * 24 + m];
    }
}

// fc2 26-chunk permutation: chunk c (0..25), band wn (0..1), tile t (0..3),
// slot s (0..7) -> original k
__host__ __device__ __forceinline__ int perm26(int c, int wn, int t, int s) {
    if (c < 16)  return (2 * c + wn) * 32 + t * 8 + s;                 // W1
    if (c < 20)  return 1024 + ((c - 16) * 8 + wn * 4 + t) * 8 + s;    // W2
    if (c == 20) return 1280 + (wn * 4 + t) * 8 + s;                   // W3
    if (c < 25)  return 1344 + ((c - 21) * 2 + wn) * 32 + t * 8 + s;   // W4
    return 1600 + (wn * 4 + t) * 8 + s;                                // W5
}

__global__ void prep_wsplit_kernel(const float* __restrict__ f1w,
                                   const float* __restrict__ f2w) {
    int i = blockIdx.x * 256 + threadIdx.x;
    if (i < 128 * 136) {
        int k = i / 136, n = i - k * 136;
        float v = (n < 128) ? f1w[k * 128 + n] : 0.f;
        ((__half*)g_w1)[i] = __float2half_rn(v);
    } else {
        int j = i - 128 * 136;
        if (j < 26 * 128 * 72) {
            int c = j / (128 * 72), r = j - c * (128 * 72);
            int krow = r / 72, col = r - krow * 72;
            float v = 0.f;
            if (col < 64) {
                int wn = col >> 5, t = (col >> 3) & 3, s = col & 7;
                v = f2w[(size_t)krow * WNUM_ + perm26(c, wn, t, s)];
            }
            ((__half*)g_w2)[(size_t)c * 9216 + krow * 72 + col] =
                __float2half_rn(v);
        }
    }
}

// ---------------------------------------------------------------------------
__launch_bounds__(THREADS, 2) __global__
void e3_main_kernel(const float* __restrict__ pair,
                    const int*   __restrict__ pidx,
                    const float* __restrict__ esh,
                    const int*   __restrict__ esrc,
                    const int*   __restrict__ edst,
                    const float* __restrict__ lng,
                    const float* __restrict__ lnb,
                    const float* __restrict__ f1b,
                    const float* __restrict__ f2b) {
    extern __shared__ char smem[];
    float* sA     = (float*)(smem + SM_A);
    float* sF     = (float*)(smem + SM_XLO);   // F staging (after fc1)
    float* f2b_s  = (float*)(smem + SM_F2B);
    float* f1b_s  = (float*)(smem + SM_F1B);
    const uint32_t smW   = smem_u32(smem + SM_W);
    const uint32_t smHHI = smem_u32(smem + SM_HHI);
    const uint32_t smXLO = smem_u32(smem + SM_XLO);

    const int tid = threadIdx.x, warp = tid >> 5, lane = tid & 31;
    const int eb0 = blockIdx.x * 64;
    const int warp_m = warp & 3, wn = warp >> 2;       // 4m x 2n
    const int gr = lane >> 2, tig = lane & 3;
    const int e0l = warp_m * 16 + gr, e1l = e0l + 8;

#define PREFETCH_CHUNK(cc) do {                                          \
    const char* gsrc_ = (const char*)g_w2 + (size_t)(cc) * CHUNK_B;      \
    _Pragma("unroll")                                                    \
    for (int u_ = 0; u_ < 5; ++u_) {                                     \
        int idx_ = tid + u_ * THREADS;                                   \
        if (idx_ < 1152) cpasync16(smW + idx_ * 16, gsrc_ + idx_ * 16);  \
    }                                                                    \
    CP_COMMIT();                                                         \
} while (0)

#define PREFETCH_W1HALF(p) do {                                          \
    const char* gsrc_ = (const char*)g_w1 + (p) * 17408;                 \
    _Pragma("unroll")                                                    \
    for (int u_ = 0; u_ < 5; ++u_) {                                     \
        int idx_ = tid + u_ * THREADS;                                   \
        if (idx_ < 1088) cpasync16(smW + idx_ * 16, gsrc_ + idx_ * 16);  \
    }                                                                    \
    CP_COMMIT();                                                         \
} while (0)

    // register-staged chunk pipeline
    uint4 pf[5];
#define LDG_CHUNK(cc) do {                                               \
    const uint4* gsrc_ = g_w2 + (size_t)(cc) * 1152;                     \
    _Pragma("unroll")                                                    \
    for (int p_ = 0; p_ < 5; ++p_) {                                     \
        int idx_ = tid + p_ * THREADS;                                   \
        if (idx_ < 1152) pf[p_] = gsrc_[idx_];                           \
    }                                                                    \
} while (0)

#define ST_CHUNK() do {                                                  \
    uint4* sdst_ = (uint4*)(smem + SM_W);                                \
    _Pragma("unroll")                                                    \
    for (int p_ = 0; p_ < 5; ++p_) {                                     \
        int idx_ = tid + p_ * THREADS;                                   \
        if (idx_ < 1152) sdst_[idx_] = pf[p_];                           \
    }                                                                    \
} while (0)

// end-of-chunk pipeline step: store staged chunk c+1, start LDG of c+2
#define CHUNK_EPI(c) do {                                                \
    __syncthreads();                                                     \
    ST_CHUNK();                                                          \
    if ((c) + 2 < 26) LDG_CHUNK((c) + 2);                                \
    __syncthreads();                                                     \
} while (0)

    // ---- prefetch fc1 weight half 0 -----------------------------------------
    PREFETCH_W1HALF(0);

    // ---- gather x into sA [64][128] f32; copy biases ------------------------
    for (int idx4 = tid; idx4 < 64 * 32; idx4 += THREADS) {
        int el = idx4 >> 5, c4 = idx4 & 31;
        int e = eb0 + el;
        int b = pidx[e], i = pidx[NE + e], j = pidx[2 * NE + e];
        ((float4*)sA)[el * 32 + c4] =
            ((const float4*)(pair + (size_t)(((b * L_) + i) * L_ + j) * DPAIR))[c4];
    }
    for (int i4 = tid; i4 < WNUM_ / 4; i4 += THREADS)
        ((float4*)f2b_s)[i4] = ((const float4*)f2b)[i4];
    if (tid < 128) f1b_s[tid] = f1b[tid];
    __syncthreads();

    // ---- LayerNorm; split x -> HHI / XLO (warp: 8 edges) --------------------
    {
        float g0 = lng[lane], g1 = lng[lane + 32], g2 = lng[lane + 64], g3 = lng[lane + 96];
        float b0 = lnb[lane], b1 = lnb[lane + 32], b2 = lnb[lane + 64], b3 = lnb[lane + 96];
        for (int ee = 0; ee < 8; ++ee) {
            int el = warp * 8 + ee;
            const float* xr = sA + el * 128;
            float x0 = xr[lane], x1 = xr[lane + 32], x2 = xr[lane + 64], x3 = xr[lane + 96];
            float s = x0 + x1 + x2 + x3;
#pragma unroll
            for (int o = 16; o > 0; o >>= 1) s += __shfl_xor_sync(0xffffffffu, s, o);
            float mu = s * (1.f / 128.f);
            float d0 = x0 - mu, d1 = x1 - mu, d2 = x2 - mu, d3 = x3 - mu;
            float q = d0 * d0 + d1 * d1 + d2 * d2 + d3 * d3;
#pragma unroll
            for (int o = 16; o > 0; o >>= 1) q += __shfl_xor_sync(0xffffffffu, q, o);
            float rstd = rsqrtf(q * (1.f / 128.f) + 1e-5f);
            float v[4] = {d0 * rstd * g0 + b0, d1 * rstd * g1 + b1,
                          d2 * rstd * g2 + b2, d3 * rstd * g3 + b3};
#pragma unroll
            for (int p = 0; p < 4; ++p) {
                int col = lane + p * 32;
                __half h = __float2half_rn(v[p]);
                __half l = __float2half_rn(v[p] - __half2float(h));
                *(__half*)(smem + SM_HHI + el * 272 + col * 2) = h;
                *(__half*)(smem + SM_XLO + el * 272 + col * 2) = l;
            }
        }
    }
    CP_WAIT(0);
    __syncthreads();   // x split visible; w1 half0 resident

    // ---- fc1: acc over 2 weight-halves; h = relu(x @ fc1_w + b) -------------
    float acc1[8][4];
#pragma unroll
    for (int t = 0; t < 8; ++t) {
        float2 bv = *(const float2*)&f1b_s[wn * 64 + t * 8 + 2 * tig];
        acc1[t][0] = bv.x; acc1[t][1] = bv.y; acc1[t][2] = bv.x; acc1[t][3] = bv.y;
    }
    const int rowsel = warp_m * 16 + (lane & 15);
    const uint32_t cex = (lane & 16) ? 16 : 0;

    // phase A: k-steps 0..3 (weight rows 0..63)
    {
        uint32_t xa[4][4], xb[4][4];
#pragma unroll
        for (int ks = 0; ks < 4; ++ks) {
            uint32_t off = rowsel * 272 + ks * 32 + cex;
            ldsm_x4(xa[ks], smHHI + off);
            ldsm_x4(xb[ks], smXLO + off);
        }
#pragma unroll
        for (int t = 0; t < 8; ++t) {
            uint32_t col2 = (wn * 64 + t * 8) * 2;
#pragma unroll
            for (int kp = 0; kp < 2; ++kp) {
                uint32_t b4[4];
                ldsm_x4t(b4, smW + (kp * 32 + lane) * 272 + col2);
                mma_f16(acc1[t], xa[2 * kp],     b4[0], b4[1]);
                mma_f16(acc1[t], xa[2 * kp + 1], b4[2], b4[3]);
                mma_f16(acc1[t], xb[2 * kp],     b4[0], b4[1]);
                mma_f16(acc1[t], xb[2 * kp + 1], b4[2], b4[3]);
            }
        }
    }
    __syncthreads();               // slot reads done
    PREFETCH_W1HALF(1);
    CP_WAIT(0);
    __syncthreads();               // w1 half1 resident

    // phase B: k-steps 4..7 (weight rows 64..127)
    {
        uint32_t xa[4][4], xb[4][4];
#pragma unroll
        for (int ks = 0; ks < 4; ++ks) {
            uint32_t off = rowsel * 272 + (4 + ks) * 32 + cex;
            ldsm_x4(xa[ks], smHHI + off);
            ldsm_x4(xb[ks], smXLO + off);
        }
        __syncthreads();           // all frag reads done before HHI overwrite
#pragma unroll
        for (int t = 0; t < 8; ++t) {
            uint32_t col2 = (wn * 64 + t * 8) * 2;
#pragma unroll
            for (int kp = 0; kp < 2; ++kp) {
                uint32_t b4[4];
                ldsm_x4t(b4, smW + (kp * 32 + lane) * 272 + col2);
                mma_f16(acc1[t], xa[2 * kp],     b4[0], b4[1]);
                mma_f16(acc1[t], xa[2 * kp + 1], b4[2], b4[3]);
                mma_f16(acc1[t], xb[2 * kp],     b4[0], b4[1]);
                mma_f16(acc1[t], xb[2 * kp + 1], b4[2], b4[3]);
            }
        }
    }
    // epilogue: relu, store h (hi only)
#pragma unroll
    for (int t = 0; t < 8; ++t) {
        int colb = wn * 64 + t * 8 + 2 * tig;
#pragma unroll
        for (int e = 0; e < 2; ++e) {
            int row = warp_m * 16 + gr + e * 8;
            float v0 = fmaxf(acc1[t][2 * e],     0.f);
            float v1 = fmaxf(acc1[t][2 * e + 1], 0.f);
            *(__half2*)(smem + SM_HHI + row * 272 + colb * 2) =
                __halves2half2(__float2half_rn(v0), __float2half_rn(v1));
        }
    }
    __syncthreads();   // fc1 done: slot free, XLO free, HHI complete

    // ---- prefetch fc2 chunk 0 (cp.async); stage F rows; A coefficients ------
    PREFETCH_CHUNK(0);

    // F staging: g_feats rows of edge dsts -> sF (pitch 64 f32)
    for (int idx4 = tid; idx4 < 64 * 16; idx4 += THREADS) {
        int el = idx4 >> 4, q = idx4 & 15;
        if (q < 14)
            ((float4*)sF)[el * 16 + q] =
                ((const float4*)(g_feats + edst[eb0 + el] * DIRR))[q];
    }
    __syncthreads();   // F staged (sync also covers sA x -> A overwrite)

#pragma unroll 1
    for (int ee = 0; ee < 8; ++ee) {
        int el = warp * 8 + ee;
        int e  = eb0 + el;
        const float* F  = sF + el * 64;
        const float* SH = esh + e * 9;
        float* Adst = sA + el * APITCH;
        for (int a = lane; a < 184; a += 32) {
            float val;
            if (a < 32) {
                val = PW0 * F[a] * SH[0];
            } else if (a < 40) {
                int u = a - 32;
                val = (PW0 * S3C) * (F[32 + u * 3] * SH[1] + F[33 + u * 3] * SH[2]
                                     + F[34 + u * 3] * SH[3]);
            } else if (a < 136) {
                int t = a - 40; int u = t / 3, m = t - u * 3;
                val = (PW1 * S3C) * F[u] * SH[1 + m];
            } else if (a < 160) {
                int t = a - 136; int u = t / 3, m = t - u * 3;
                val = (PW1 * S3C) * F[32 + u * 3 + m] * SH[0];
            } else {
                int t = a - 160; int u = t / 3, m = t - u * 3;
                float xx = F[32 + u * 3], xy = F[33 + u * 3], xz = F[34 + u * 3];
                float s0 = SH[4], s1 = SH[5], s2 = SH[6], s3v = SH[7], s4 = SH[8];
                float t5;
                if (m == 0)      t5 = (xz * s0 + xy * s1 - xx * s4) * S3C - xx * s2 * (1.f / 3.f);
                else if (m == 1) t5 = (xx * s1 + xz * s3v) * S3C + xy * s2 * (2.f / 3.f);
                else             t5 = (xx * s0 + xy * s3v + xz * s4) * S3C - xz * s2 * (1.f / 3.f);
                val = (PW1 * F121) * t5;
            }
            Adst[a] = val;
        }
    }

    // h fragments (reused across all 26 chunks)
    uint32_t xh[8][4];
#pragma unroll
    for (int ks = 0; ks < 8; ++ks)
        ldsm_x4(xh[ks], smHHI + rowsel * 272 + ks * 32 + cex);

    // start register pipeline: chunk 1 -> regs while chunk 0 lands in smem
    LDG_CHUNK(1);
    CP_WAIT(0);
    __syncthreads();   // A complete; chunk 0 resident

    float conv0[16];
#pragma unroll
    for (int o = 0; o < 16; ++o) conv0[o] = 0.f;
    float conv1[12];
#pragma unroll
    for (int o = 0; o < 12; ++o) conv1[o] = 0.f;
    const float* A0r = sA + e0l * APITCH;
    const float* A1r = sA + e1l * APITCH;

#define CHUNK_MMA(ACC, COL2)                                             \
    { uint32_t b4_[4];                                                   \
      _Pragma("unroll")                                                  \
      for (int kp_ = 0; kp_ < 4; ++kp_) {                                \
          ldsm_x4t(b4_, smW + (kp_ * 32 + lane) * 144 + (COL2));         \
          mma_f16(ACC, xh[2 * kp_],     b4_[0], b4_[1]);                 \
          mma_f16(ACC, xh[2 * kp_ + 1], b4_[2], b4_[3]);                 \
      } }

    // ---- W1: chunks 0..15 -> conv0 ------------------------------------------
#pragma unroll 1
    for (int c = 0; c < 16; ++c) {
        const int u = 2 * c + wn;
        float a0 = A0r[u], a1 = A1r[u];
#pragma unroll
        for (int t = 0; t < 4; ++t) {
            float2 bv = *(const float2*)&f2b_s[u * 32 + t * 8 + 2 * tig];
            float acc[4] = {bv.x, bv.y, bv.x, bv.y};
            CHUNK_MMA(acc, (wn * 32 + t * 8) * 2);
            conv0[t * 4 + 0] += a0 * acc[0]; conv0[t * 4 + 1] += a0 * acc[1];
            conv0[t * 4 + 2] += a1 * acc[2]; conv0[t * 4 + 3] += a1 * acc[3];
        }
        CHUNK_EPI(c);
    }
    // ---- W2: chunks 16..19 -> conv1 ------------------------------------------
#pragma unroll 1
    for (int c = 16; c < 20; ++c) {
        const int ub = (c - 16) * 8 + wn * 4;
#pragma unroll
        for (int t = 0; t < 4; ++t) {
            const int u = ub + t;
            float2 bv = *(const float2*)&f2b_s[1024 + u * 8 + 2 * tig];
            float acc[4] = {bv.x, bv.y, bv.x, bv.y};
            CHUNK_MMA(acc, (wn * 32 + t * 8) * 2);
            const float* A0 = A0r + 40 + u * 3;
            const float* A1 = A1r + 40 + u * 3;
#pragma unroll
            for (int m = 0; m < 3; ++m) {
                conv1[m]     += A0[m] * acc[0];
                conv1[3 + m] += A0[m] * acc[1];
                conv1[6 + m] += A1[m] * acc[2];
                conv1[9 + m] += A1[m] * acc[3];
            }
        }
        CHUNK_EPI(c);
    }
    // ---- W3: chunk 20 -> conv1 ------------------------------------------------
    {
#pragma unroll
        for (int t = 0; t < 4; ++t) {
            const int u = wn * 4 + t;
            float2 bv = *(const float2*)&f2b_s[1280 + u * 8 + 2 * tig];
            float acc[4] = {bv.x, bv.y, bv.x, bv.y};
            CHUNK_MMA(acc, (wn * 32 + t * 8) * 2);
            const float* A0 = A0r + 136 + u * 3;
            const float* A1 = A1r + 136 + u * 3;
#pragma unroll
            for (int m = 0; m < 3; ++m) {
                conv1[m]     += A0[m] * acc[0];
                conv1[3 + m] += A0[m] * acc[1];
                conv1[6 + m] += A1[m] * acc[2];
                conv1[9 + m] += A1[m] * acc[3];
            }
        }
        CHUNK_EPI(20);
    }
    // ---- W4: chunks 21..24 -> conv0 --------------------------------------------
#pragma unroll 1
    for (int c = 21; c < 25; ++c) {
        const int uu = (c - 21) * 2 + wn;
        float a0 = A0r[32 + uu], a1 = A1r[32 + uu];
#pragma unroll
        for (int t = 0; t < 4; ++t) {
            float2 bv = *(const float2*)&f2b_s[1344 + uu * 32 + t * 8 + 2 * tig];
            float acc[4] = {bv.x, bv.y, bv.x, bv.y};
            CHUNK_MMA(acc, (wn * 32 + t * 8) * 2);
            conv0[t * 4 + 0] += a0 * acc[0]; conv0[t * 4 + 1] += a0 * acc[1];
            conv0[t * 4 + 2] += a1 * acc[2]; conv0[t * 4 + 3] += a1 * acc[3];
        }
        CHUNK_EPI(c);
    }
    // ---- W5: chunk 25 -> conv1 --------------------------------------------------
    {
#pragma unroll
        for (int t = 0; t < 4; ++t) {
            const int u = wn * 4 + t;
            float2 bv = *(const float2*)&f2b_s[1600 + u * 8 + 2 * tig];
            float acc[4] = {bv.x, bv.y, bv.x, bv.y};
            CHUNK_MMA(acc, (wn * 32 + t * 8) * 2);
            const float* A0 = A0r + 160 + u * 3;
            const float* A1 = A1r + 160 + u * 3;
#pragma unroll
            for (int m = 0; m < 3; ++m) {
                conv1[m]     += A0[m] * acc[0];
                conv1[3 + m] += A0[m] * acc[1];
                conv1[6 + m] += A1[m] * acc[2];
                conv1[9 + m] += A1[m] * acc[3];
            }
        }
    }

    // ---- epilogue: scatter-add -----------------------------------------------
    {
        int s0 = esrc[eb0 + e0l] * DIRR;
        int s1 = esrc[eb0 + e1l] * DIRR;
#pragma unroll
        for (int t = 0; t < 4; ++t)
#pragma unroll
            for (int j = 0; j < 2; ++j) {
                int v = t * 8 + 2 * tig + j;
                atomicAdd(&g_sums[s0 + v], conv0[t * 4 + j]);
                atomicAdd(&g_sums[s1 + v], conv0[t * 4 + 2 + j]);
            }
#pragma unroll
        for (int j = 0; j < 2; ++j)
#pragma unroll
            for (int m = 0; m < 3; ++m) {
                int o = 32 + (2 * tig + j) * 3 + m;
                atomicAdd(&g_sums[s0 + o], conv1[j * 3 + m]);
                atomicAdd(&g_sums[s1 + o], conv1[6 + j * 3 + m]);
            }
    }
    if (tid < 64) atomicAdd(&g_cnt[esrc[eb0 + tid]], 1.f);
}

// ---------------------------------------------------------------------------
__global__ void finalize_kernel(const float* __restrict__ node,
                                const float* __restrict__ l1,
                                const float* __restrict__ pnw,
                                const float* __restrict__ pnb,
                                float* __restrict__ out) {
    int n = blockIdx.x;
    __shared__ float o0[32];
    float inv = 1.f / fmaxf(g_cnt[n], 1.f);
    if (threadIdx.x < 32) o0[threadIdx.x] = g_sums[n * DIRR + threadIdx.x] * inv;
    __syncthreads();
    int d = threadIdx.x;
    float acc = pnb[d];
#pragma unroll
    for (int u = 0; u < 32; ++u) acc += o0[u] * pnw[u * DNODE + d];
    out[n * DNODE + d] = acc + node[n * DNODE + d];
    if (d < 24)
        out[NNODE * DNODE + n * 24 + d] = g_sums[n * DIRR + 32 + d] * inv + l1[n * 24 + d];
}

// ---------------------------------------------------------------------------
extern "C" void kernel_launch(void* const* d_in, const int* in_sizes, int n_in,
                              void* d_out, int out_size) {
    const float* node = (const float*)d_in[0];
    const float* pair = (const float*)d_in[1];
    const float* l1   = (const float*)d_in[2];
    const float* esh  = (const float*)d_in[3];
    const float* pl0w = (const float*)d_in[4];
    const float* pl0b = (const float*)d_in[5];
    const float* pnw  = (const float*)d_in[6];
    const float* pnb  = (const float*)d_in[7];
    const float* lng  = (const float*)d_in[8];
    const float* lnb  = (const float*)d_in[9];
    const float* f1w  = (const float*)d_in[10];
    const float* f1b  = (const float*)d_in[11];
    const float* f2w  = (const float*)d_in[12];
    const float* f2b  = (const float*)d_in[13];
    const int*   pidx = (const int*)d_in[14];
    const int*   esrc = (const int*)d_in[15];
    const int*   edst = (const int*)d_in[16];
    float* out = (float*)d_out;

    cudaFuncSetAttribute(e3_main_kernel,
                         cudaFuncAttributeMaxDynamicSharedMemorySize, SM_TOTAL);

    prep_zero_kernel<<<57, 1024>>>();
    prep_proj_kernel<<<64, 256>>>(node, pl0w, pl0b, l1);
    prep_wsplit_kernel<<<1004, 256>>>(f1w, f2w);
    e3_main_kernel<<<NE / 64, THREADS, SM_TOTAL>>>(pair, pidx, esh, esrc, edst,
                                                   lng, lnb, f1b, f2b);
    finalize_kernel<<<NNODE, 256>>>(node, l1, pnw, pnb, out);
}

// round 16
// speedup vs baseline: 1.0446x; 1.0446x over previous
#include <cuda_runtime.h>
#include <cuda_fp16.h>
#include <cstdint>

#define B_     4
#define L_     256
#define NNODE  1024
#define DNODE  256
#define DPAIR  128
#define NE     65536
#define M0_    32
#define DIRR   56
#define WNUM_  1664

#define PW0   0.15811388300841897f
#define PW1   0.25f
#define S3C   0.5773502691896258f
#define F121  0.5477225575051661f

// device scratch (no allocations allowed)
__device__ float g_feats[NNODE * DIRR];
__device__ float g_sums [NNODE * DIRR];
__device__ float g_cnt  [NNODE];
// fp16 weights: fc1 plain (pitch 136); fc2 26-chunk 64-col permuted, pitch 72
__device__ uint4 g_w1[2176];     // 128 x 136 fp16 = 34,816 B
__device__ uint4 g_w2[29952];    // 26 x 128 x 72 fp16 = 479,232 B

// ---------------- plain-PTX helpers (sm_80-level, safe on sm_103) ----------
__device__ __forceinline__ uint32_t smem_u32(const void* p) {
    uint32_t a;
    asm("{ .reg .u64 t; cvta.to.shared.u64 t, %1; cvt.u32.u64 %0, t; }"
        : "=r"(a) : "l"(p));
    return a;
}
__device__ __forceinline__ void ldsm_x4(uint32_t* r, uint32_t addr) {
    asm volatile("ldmatrix.sync.aligned.m8n8.x4.shared.b16 {%0,%1,%2,%3}, [%4];"
        : "=r"(r[0]), "=r"(r[1]), "=r"(r[2]), "=r"(r[3]) : "r"(addr));
}
__device__ __forceinline__ void ldsm_x4t(uint32_t* r, uint32_t addr) {
    asm volatile("ldmatrix.sync.aligned.m8n8.x4.trans.shared.b16 {%0,%1,%2,%3}, [%4];"
        : "=r"(r[0]), "=r"(r[1]), "=r"(r[2]), "=r"(r[3]) : "r"(addr));
}
__device__ __forceinline__ void mma_f16(float* d, const uint32_t* a,
                                        uint32_t b0, uint32_t b1) {
    asm volatile("mma.sync.aligned.m16n8k16.row.col.f32.f16.f16.f32 "
        "{%0,%1,%2,%3}, {%4,%5,%6,%7}, {%8,%9}, {%0,%1,%2,%3};"
        : "+f"(d[0]), "+f"(d[1]), "+f"(d[2]), "+f"(d[3])
        : "r"(a[0]), "r"(a[1]), "r"(a[2]), "r"(a[3]), "r"(b0), "r"(b1));
}
__device__ __forceinline__ void cpasync16(uint32_t s, const void* g) {
    asm volatile("cp.async.cg.shared.global [%0], [%1], 16;" :: "r"(s), "l"(g));
}
#define CP_COMMIT() asm volatile("cp.async.commit_group;" ::: "memory")
#define CP_WAIT(N)  asm volatile("cp.async.wait_group %0;" :: "n"(N) : "memory")

// smem layout (bytes) -- 64 edges per CTA, 2 CTAs per SM
#define CHUNK_B  18432    // fc2 chunk: 128 rows x 72 fp16 (pitch 144, 16B-aligned)
#define SM_W0    0        // slot0: fc1w halves, then even fc2 chunks
#define SM_W1    18432    // slot1: x-lo during fc1 (17408 <= 18432), then odd chunks
#define SM_HHI   36864    // 64 x 136 fp16, pitch 272
#define SM_A     54272    // x f32 staging 64x128 (32768); then A coeffs 64x185 f32
#define SM_F2B   101632   // 1664 f32
#define SM_F1B   108288   // 128 f32
#define SM_TOTAL 108800

#define THREADS  256
#define APITCH   185

// ---------------------------------------------------------------------------
__global__ void prep_zero_kernel() {
    int i = blockIdx.x * 1024 + threadIdx.x;
    if (i < NNODE * DIRR) g_sums[i] = 0.f;
    else if (i < NNODE * DIRR + NNODE) g_cnt[i - NNODE * DIRR] = 0.f;
}

__global__ __launch_bounds__(256) void prep_proj_kernel(
        const float* __restrict__ node, const float* __restrict__ w,
        const float* __restrict__ b,    const float* __restrict__ l1) {
    __shared__ float sw[DNODE * M0_];
    __shared__ float sx[16 * DNODE];
    int tid = threadIdx.x, n0 = blockIdx.x * 16;
    for (int i = tid; i < DNODE * M0_; i += 256) sw[i] = w[i];
    for (int i = tid; i < 16 * DNODE; i += 256) sx[i] = node[n0 * DNODE + i];
    __syncthreads();
    int warp = tid >> 5, lane = tid & 31;
    for (int r = 0; r < 2; ++r) {
        int nl = warp * 2 + r;
        float acc = b[lane];
        const float* x = sx + nl * DNODE;
#pragma unroll 8
        for (int k = 0; k < DNODE; ++k) acc += x[k] * sw[k * M0_ + lane];
        g_feats[(n0 + nl) * DIRR + lane] = acc;
    }
    for (int i = tid; i < 16 * 24; i += 256) {
        int nl = i / 24, m = i - nl * 24;
        g_feats[(n0 + nl) * DIRR + M0_ + m] = l1[(n0 + nl) * 24 + m];
    }
}

// fc2 26-chunk permutation: chunk c (0..25), band wn (0..1), tile t (0..3),
// slot s (0..7) -> original k
__host__ __device__ __forceinline__ int perm26(int c, int wn, int t, int s) {
    if (c < 16)  return (2 * c + wn) * 32 + t * 8 + s;                 // W1
    if (c < 20)  return 1024 + ((c - 16) * 8 + wn * 4 + t) * 8 + s;    // W2
    if (c == 20) return 1280 + (wn * 4 + t) * 8 + s;                   // W3
    if (c < 25)  return 1344 + ((c - 21) * 2 + wn) * 32 + t * 8 + s;   // W4
    return 1600 + (wn * 4 + t) * 8 + s;                                // W5
}

__global__ void prep_wsplit_kernel(const float* __restrict__ f1w,
                                   const float* __restrict__ f2w) {
    int i = blockIdx.x * 256 + threadIdx.x;
    if (i < 128 * 136) {
        int k = i / 136, n = i - k * 136;
        float v = (n < 128) ? f1w[k * 128 + n] : 0.f;
        ((__half*)g_w1)[i] = __float2half_rn(v);
    } else {
        int j = i - 128 * 136;
        if (j < 26 * 128 * 72) {
            int c = j / (128 * 72), r = j - c * (128 * 72);
            int krow = r / 72, col = r - krow * 72;
            float v = 0.f;
            if (col < 64) {
                int wn = col >> 5, t = (col >> 3) & 3, s = col & 7;
                v = f2w[(size_t)krow * WNUM_ + perm26(c, wn, t, s)];
            }
            ((__half*)g_w2)[(size_t)c * 9216 + krow * 72 + col] =
                __float2half_rn(v);
        }
    }
}

// ---------------------------------------------------------------------------
__launch_bounds__(THREADS, 2) __global__
void e3_main_kernel(const float* __restrict__ pair,
                    const int*   __restrict__ pidx,
                    const float* __restrict__ esh,
                    const int*   __restrict__ esrc,
                    const int*   __restrict__ edst,
                    const float* __restrict__ lng,
                    const float* __restrict__ lnb,
                    const float* __restrict__ f1b,
                    const float* __restrict__ f2b) {
    extern __shared__ char smem[];
    float* sA     = (float*)(smem + SM_A);
    float* f2b_s  = (float*)(smem + SM_F2B);
    float* f1b_s  = (float*)(smem + SM_F1B);
    const uint32_t smW0  = smem_u32(smem + SM_W0);
    const uint32_t smHHI = smem_u32(smem + SM_HHI);
    const uint32_t smXLO = smW0 + SM_W1;   // x-lo lives in slot1 during fc1

    const int tid = threadIdx.x, warp = tid >> 5, lane = tid & 31;
    const int eb0 = blockIdx.x * 64;
    const int warp_m = warp & 3, wn = warp >> 2;       // 4m x 2n
    const int gr = lane >> 2, tig = lane & 3;
    const int e0l = warp_m * 16 + gr, e1l = e0l + 8;

// prefetch fc2 chunk cc into slot (cc&1): 1152 uint4
#define PREFETCH_CHUNK(cc) do {                                          \
    const char* gsrc_ = (const char*)g_w2 + (size_t)(cc) * CHUNK_B;      \
    uint32_t sdst_ = smW0 + (uint32_t)(((cc) & 1) * CHUNK_B);            \
    _Pragma("unroll")                                                    \
    for (int u_ = 0; u_ < 5; ++u_) {                                     \
        int idx_ = tid + u_ * THREADS;                                   \
        if (idx_ < 1152) cpasync16(sdst_ + idx_ * 16, gsrc_ + idx_ * 16);\
    }                                                                    \
    CP_COMMIT();                                                         \
} while (0)

#define PREFETCH_W1HALF(p) do {                                          \
    const char* gsrc_ = (const char*)g_w1 + (p) * 17408;                 \
    _Pragma("unroll")                                                    \
    for (int u_ = 0; u_ < 5; ++u_) {                                     \
        int idx_ = tid + u_ * THREADS;                                   \
        if (idx_ < 1088) cpasync16(smW0 + idx_ * 16, gsrc_ + idx_ * 16); \
    }                                                                    \
    CP_COMMIT();                                                         \
} while (0)

#define CHUNK_PRE(c) do {                                                \
    if ((c) < 25) { CP_WAIT(1); } else { CP_WAIT(0); }                   \
    __syncthreads();                                                     \
} while (0)

#define CHUNK_POST(c) do {                                               \
    __syncthreads();                                                     \
    if ((c) + 2 < 26) PREFETCH_CHUNK((c) + 2);                           \
} while (0)

    // ---- prefetch fc1 weight half 0 into slot0 ------------------------------
    PREFETCH_W1HALF(0);

    // ---- gather x into sA [64][128] f32; copy biases ------------------------
    for (int idx4 = tid; idx4 < 64 * 32; idx4 += THREADS) {
        int el = idx4 >> 5, c4 = idx4 & 31;
        int e = eb0 + el;
        int b = pidx[e], i = pidx[NE + e], j = pidx[2 * NE + e];
        ((float4*)sA)[el * 32 + c4] =
            ((const float4*)(pair + (size_t)(((b * L_) + i) * L_ + j) * DPAIR))[c4];
    }
    for (int i4 = tid; i4 < WNUM_ / 4; i4 += THREADS)
        ((float4*)f2b_s)[i4] = ((const float4*)f2b)[i4];
    if (tid < 128) f1b_s[tid] = f1b[tid];
    __syncthreads();

    // ---- LayerNorm; split x -> HHI / XLO(slot1) (warp: 8 edges) -------------
    {
        float g0 = lng[lane], g1 = lng[lane + 32], g2 = lng[lane + 64], g3 = lng[lane + 96];
        float b0 = lnb[lane], b1 = lnb[lane + 32], b2 = lnb[lane + 64], b3 = lnb[lane + 96];
        for (int ee = 0; ee < 8; ++ee) {
            int el = warp * 8 + ee;
            const float* xr = sA + el * 128;
            float x0 = xr[lane], x1 = xr[lane + 32], x2 = xr[lane + 64], x3 = xr[lane + 96];
            float s = x0 + x1 + x2 + x3;
#pragma unroll
            for (int o = 16; o > 0; o >>= 1) s += __shfl_xor_sync(0xffffffffu, s, o);
            float mu = s * (1.f / 128.f);
            float d0 = x0 - mu, d1 = x1 - mu, d2 = x2 - mu, d3 = x3 - mu;
            float q = d0 * d0 + d1 * d1 + d2 * d2 + d3 * d3;
#pragma unroll
            for (int o = 16; o > 0; o >>= 1) q += __shfl_xor_sync(0xffffffffu, q, o);
            float rstd = rsqrtf(q * (1.f / 128.f) + 1e-5f);
            float v[4] = {d0 * rstd * g0 + b0, d1 * rstd * g1 + b1,
                          d2 * rstd * g2 + b2, d3 * rstd * g3 + b3};
#pragma unroll
            for (int p = 0; p < 4; ++p) {
                int col = lane + p * 32;
                __half h = __float2half_rn(v[p]);
                __half l = __float2half_rn(v[p] - __half2float(h));
                *(__half*)(smem + SM_HHI + el * 272 + col * 2) = h;
                *(__half*)(smem + SM_W1  + el * 272 + col * 2) = l;
            }
        }
    }
    CP_WAIT(0);
    __syncthreads();   // x split visible; w1 half0 resident

    // ---- fc1: acc over 2 weight-halves; h = relu(x @ fc1_w + b) -------------
    float acc1[8][4];
#pragma unroll
    for (int t = 0; t < 8; ++t) {
        float2 bv = *(const float2*)&f1b_s[wn * 64 + t * 8 + 2 * tig];
        acc1[t][0] = bv.x; acc1[t][1] = bv.y; acc1[t][2] = bv.x; acc1[t][3] = bv.y;
    }
    const int rowsel = warp_m * 16 + (lane & 15);
    const uint32_t cex = (lane & 16) ? 16 : 0;

    // phase A: k-steps 0..3 (weight rows 0..63)
    {
        uint32_t xa[4][4], xb[4][4];
#pragma unroll
        for (int ks = 0; ks < 4; ++ks) {
            uint32_t off = rowsel * 272 + ks * 32 + cex;
            ldsm_x4(xa[ks], smHHI + off);
            ldsm_x4(xb[ks], smXLO + off);
        }
#pragma unroll
        for (int t = 0; t < 8; ++t) {
            uint32_t col2 = (wn * 64 + t * 8) * 2;
#pragma unroll
            for (int kp = 0; kp < 2; ++kp) {
                uint32_t b4[4];
                ldsm_x4t(b4, smW0 + (kp * 32 + lane) * 272 + col2);
                mma_f16(acc1[t], xa[2 * kp],     b4[0], b4[1]);
                mma_f16(acc1[t], xa[2 * kp + 1], b4[2], b4[3]);
                mma_f16(acc1[t], xb[2 * kp],     b4[0], b4[1]);
                mma_f16(acc1[t], xb[2 * kp + 1], b4[2], b4[3]);
            }
        }
    }
    __syncthreads();               // slot0 reads done
    PREFETCH_W1HALF(1);
    CP_WAIT(0);
    __syncthreads();               // w1 half1 resident

    // phase B: k-steps 4..7 (weight rows 64..127)
    {
        uint32_t xa[4][4], xb[4][4];
#pragma unroll
        for (int ks = 0; ks < 4; ++ks) {
            uint32_t off = rowsel * 272 + (4 + ks) * 32 + cex;
            ldsm_x4(xa[ks], smHHI + off);
            ldsm_x4(xb[ks], smXLO + off);
        }
        __syncthreads();           // all frag reads done before HHI overwrite
#pragma unroll
        for (int t = 0; t < 8; ++t) {
            uint32_t col2 = (wn * 64 + t * 8) * 2;
#pragma unroll
            for (int kp = 0; kp < 2; ++kp) {
                uint32_t b4[4];
                ldsm_x4t(b4, smW0 + (kp * 32 + lane) * 272 + col2);
                mma_f16(acc1[t], xa[2 * kp],     b4[0], b4[1]);
                mma_f16(acc1[t], xa[2 * kp + 1], b4[2], b4[3]);
                mma_f16(acc1[t], xb[2 * kp],     b4[0], b4[1]);
                mma_f16(acc1[t], xb[2 * kp + 1], b4[2], b4[3]);
            }
        }
    }
    // epilogue: relu, store h (hi only)
#pragma unroll
    for (int t = 0; t < 8; ++t) {
        int colb = wn * 64 + t * 8 + 2 * tig;
#pragma unroll
        for (int e = 0; e < 2; ++e) {
            int row = warp_m * 16 + gr + e * 8;
            float v0 = fmaxf(acc1[t][2 * e],     0.f);
            float v1 = fmaxf(acc1[t][2 * e + 1], 0.f);
            *(__half2*)(smem + SM_HHI + row * 272 + colb * 2) =
                __halves2half2(__float2half_rn(v0), __float2half_rn(v1));
        }
    }
    __syncthreads();   // fc1 done: both slots free, HHI complete

    // ---- prefetch fc2 chunks 0 and 1 (double buffer) ------------------------
    PREFETCH_CHUNK(0);
    PREFETCH_CHUNK(1);

    // ---- A coefficients (direct g_feats reads; x in sA dead) ----------------
#pragma unroll 1
    for (int ee = 0; ee < 8; ++ee) {
        int el = warp * 8 + ee;
        int e  = eb0 + el;
        const float* F  = g_feats + edst[e] * DIRR;
        const float* SH = esh + e * 9;
        float* Adst = sA + el * APITCH;
        for (int a = lane; a < 184; a += 32) {
            float val;
            if (a < 32) {
                val = PW0 * F[a] * SH[0];
            } else if (a < 40) {
                int u = a - 32;
                val = (PW0 * S3C) * (F[32 + u * 3] * SH[1] + F[33 + u * 3] * SH[2]
                                     + F[34 + u * 3] * SH[3]);
            } else if (a < 136) {
                int t = a - 40; int u = t / 3, m = t - u * 3;
                val = (PW1 * S3C) * F[u] * SH[1 + m];
            } else if (a < 160) {
                int t = a - 136; int u = t / 3, m = t - u * 3;
                val = (PW1 * S3C) * F[32 + u * 3 + m] * SH[0];
            } else {
                int t = a - 160; int u = t / 3, m = t - u * 3;
                float xx = F[32 + u * 3], xy = F[33 + u * 3], xz = F[34 + u * 3];
                float s0 = SH[4], s1 = SH[5], s2 = SH[6], s3v = SH[7], s4 = SH[8];
                float t5;
                if (m == 0)      t5 = (xz * s0 + xy * s1 - xx * s4) * S3C - xx * s2 * (1.f / 3.f);
                else if (m == 1) t5 = (xx * s1 + xz * s3v) * S3C + xy * s2 * (2.f / 3.f);
                else             t5 = (xx * s0 + xy * s3v + xz * s4) * S3C - xz * s2 * (1.f / 3.f);
                val = (PW1 * F121) * t5;
            }
            Adst[a] = val;
        }
    }

    // h fragments (reused across all 26 chunks)
    uint32_t xh[8][4];
#pragma unroll
    for (int ks = 0; ks < 8; ++ks)
        ldsm_x4(xh[ks], smHHI + rowsel * 272 + ks * 32 + cex);

    float conv0[16];
#pragma unroll
    for (int o = 0; o < 16; ++o) conv0[o] = 0.f;
    float conv1[12];
#pragma unroll
    for (int o = 0; o < 12; ++o) conv1[o] = 0.f;
    const float* A0r = sA + e0l * APITCH;
    const float* A1r = sA + e1l * APITCH;

#define CHUNK_MMA(ACC, BUF, COL2)                                        \
    { uint32_t b4_[4];                                                   \
      _Pragma("unroll")                                                  \
      for (int kp_ = 0; kp_ < 4; ++kp_) {                                \
          ldsm_x4t(b4_, (BUF) + (kp_ * 32 + lane) * 144 + (COL2));       \
          mma_f16(ACC, xh[2 * kp_],     b4_[0], b4_[1]);                 \
          mma_f16(ACC, xh[2 * kp_ + 1], b4_[2], b4_[3]);                 \
      } }

    // ---- W1: chunks 0..15 -> conv0 ------------------------------------------
#pragma unroll 1
    for (int c = 0; c < 16; ++c) {
        CHUNK_PRE(c);
        const uint32_t buf = smW0 + (uint32_t)((c & 1) * CHUNK_B);
        const int u = 2 * c + wn;
        float a0 = A0r[u], a1 = A1r[u];
#pragma unroll
        for (int t = 0; t < 4; ++t) {
            float2 bv = *(const float2*)&f2b_s[u * 32 + t * 8 + 2 * tig];
            float acc[4] = {bv.x, bv.y, bv.x, bv.y};
            CHUNK_MMA(acc, buf, (wn * 32 + t * 8) * 2);
            conv0[t * 4 + 0] += a0 * acc[0]; conv0[t * 4 + 1] += a0 * acc[1];
            conv0[t * 4 + 2] += a1 * acc[2]; conv0[t * 4 + 3] += a1 * acc[3];
        }
        CHUNK_POST(c);
    }
    // ---- W2: chunks 16..19 -> conv1 ------------------------------------------
#pragma unroll 1
    for (int c = 16; c < 20; ++c) {
        CHUNK_PRE(c);
        const uint32_t buf = smW0 + (uint32_t)((c & 1) * CHUNK_B);
        const int ub = (c - 16) * 8 + wn * 4;
#pragma unroll
        for (int t = 0; t < 4; ++t) {
            const int u = ub + t;
            float2 bv = *(const float2*)&f2b_s[1024 + u * 8 + 2 * tig];
            float acc[4] = {bv.x, bv.y, bv.x, bv.y};
            CHUNK_MMA(acc, buf, (wn * 32 + t * 8) * 2);
            const float* A0 = A0r + 40 + u * 3;
            const float* A1 = A1r + 40 + u * 3;
#pragma unroll
            for (int m = 0; m < 3; ++m) {
                conv1[m]     += A0[m] * acc[0];
                conv1[3 + m] += A0[m] * acc[1];
                conv1[6 + m] += A1[m] * acc[2];
                conv1[9 + m] += A1[m] * acc[3];
            }
        }
        CHUNK_POST(c);
    }
    // ---- W3: chunk 20 -> conv1 ------------------------------------------------
    {
        CHUNK_PRE(20);
        const uint32_t buf = smW0;   // 20 even -> slot0
#pragma unroll
        for (int t = 0; t < 4; ++t) {
            const int u = wn * 4 + t;
            float2 bv = *(const float2*)&f2b_s[1280 + u * 8 + 2 * tig];
            float acc[4] = {bv.x, bv.y, bv.x, bv.y};
            CHUNK_MMA(acc, buf, (wn * 32 + t * 8) * 2);
            const float* A0 = A0r + 136 + u * 3;
            const float* A1 = A1r + 136 + u * 3;
#pragma unroll
            for (int m = 0; m < 3; ++m) {
                conv1[m]     += A0[m] * acc[0];
                conv1[3 + m] += A0[m] * acc[1];
                conv1[6 + m] += A1[m] * acc[2];
                conv1[9 + m] += A1[m] * acc[3];
            }
        }
        CHUNK_POST(20);
    }
    // ---- W4: chunks 21..24 -> conv0 --------------------------------------------
#pragma unroll 1
    for (int c = 21; c < 25; ++c) {
        CHUNK_PRE(c);
        const uint32_t buf = smW0 + (uint32_t)((c & 1) * CHUNK_B);
        const int uu = (c - 21) * 2 + wn;
        float a0 = A0r[32 + uu], a1 = A1r[32 + uu];
#pragma unroll
        for (int t = 0; t < 4; ++t) {
            float2 bv = *(const float2*)&f2b_s[1344 + uu * 32 + t * 8 + 2 * tig];
            float acc[4] = {bv.x, bv.y, bv.x, bv.y};
            CHUNK_MMA(acc, buf, (wn * 32 + t * 8) * 2);
            conv0[t * 4 + 0] += a0 * acc[0]; conv0[t * 4 + 1] += a0 * acc[1];
            conv0[t * 4 + 2] += a1 * acc[2]; conv0[t * 4 + 3] += a1 * acc[3];
        }
        CHUNK_POST(c);
    }
    // ---- W5: chunk 25 -> conv1 --------------------------------------------------
    {
        CHUNK_PRE(25);
        const uint32_t buf = smW0 + CHUNK_B;   // 25 odd -> slot1
#pragma unroll
        for (int t = 0; t < 4; ++t) {
            const int u = wn * 4 + t;
            float2 bv = *(const float2*)&f2b_s[1600 + u * 8 + 2 * tig];
            float acc[4] = {bv.x, bv.y, bv.x, bv.y};
            CHUNK_MMA(acc, buf, (wn * 32 + t * 8) * 2);
            const float* A0 = A0r + 160 + u * 3;
            const float* A1 = A1r + 160 + u * 3;
#pragma unroll
            for (int m = 0; m < 3; ++m) {
                conv1[m]     += A0[m] * acc[0];
                conv1[3 + m] += A0[m] * acc[1];
                conv1[6 + m] += A1[m] * acc[2];
                conv1[9 + m] += A1[m] * acc[3];
            }
        }
    }

    // ---- epilogue: scatter-add -----------------------------------------------
    {
        int s0 = esrc[eb0 + e0l] * DIRR;
        int s1 = esrc[eb0 + e1l] * DIRR;
#pragma unroll
        for (int t = 0; t < 4; ++t)
#pragma unroll
            for (int j = 0; j < 2; ++j) {
                int v = t * 8 + 2 * tig + j;
                atomicAdd(&g_sums[s0 + v], conv0[t * 4 + j]);
                atomicAdd(&g_sums[s1 + v], conv0[t * 4 + 2 + j]);
            }
#pragma unroll
        for (int j = 0; j < 2; ++j)
#pragma unroll
            for (int m = 0; m < 3; ++m) {
                int o = 32 + (2 * tig + j) * 3 + m;
                atomicAdd(&g_sums[s0 + o], conv1[j * 3 + m]);
                atomicAdd(&g_sums[s1 + o], conv1[6 + j * 3 + m]);
            }
    }
    if (tid < 64) atomicAdd(&g_cnt[esrc[eb0 + tid]], 1.f);
}

// ---------------------------------------------------------------------------
__global__ void finalize_kernel(const float* __restrict__ node,
                                const float* __restrict__ l1,
                                const float* __restrict__ pnw,
                                const float* __restrict__ pnb,
                                float* __restrict__ out) {
    int n = blockIdx.x;
    __shared__ float o0[32];
    float inv = 1.f / fmaxf(g_cnt[n], 1.f);
    if (threadIdx.x < 32) o0[threadIdx.x] = g_sums[n * DIRR + threadIdx.x] * inv;
    __syncthreads();
    int d = threadIdx.x;
    float acc = pnb[d];
#pragma unroll
    for (int u = 0; u < 32; ++u) acc += o0[u] * pnw[u * DNODE + d];
    out[n * DNODE + d] = acc + node[n * DNODE + d];
    if (d < 24)
        out[NNODE * DNODE + n * 24 + d] = g_sums[n * DIRR + 32 + d] * inv + l1[n * 24 + d];
}

// ---------------------------------------------------------------------------
extern "C" void kernel_launch(void* const* d_in, const int* in_sizes, int n_in,
                              void* d_out, int out_size) {
    const float* node = (const float*)d_in[0];
    const float* pair = (const float*)d_in[1];
    const float* l1   = (const float*)d_in[2];
    const float* esh  = (const float*)d_in[3];
    const float* pl0w = (const float*)d_in[4];
    const float* pl0b = (const float*)d_in[5];
    const float* pnw  = (const float*)d_in[6];
    const float* pnb  = (const float*)d_in[7];
    const float* lng  = (const float*)d_in[8];
    const float* lnb  = (const float*)d_in[9];
    const float* f1w  = (const float*)d_in[10];
    const float* f1b  = (const float*)d_in[11];
    const float* f2w  = (const float*)d_in[12];
    const float* f2b  = (const float*)d_in[13];
    const int*   pidx = (const int*)d_in[14];
    const int*   esrc = (const int*)d_in[15];
    const int*   edst = (const int*)d_in[16];
    float* out = (float*)d_out;

    cudaFuncSetAttribute(e3_main_kernel,
                         cudaFuncAttributeMaxDynamicSharedMemorySize, SM_TOTAL);

    prep_zero_kernel<<<57, 1024>>>();
    prep_proj_kernel<<<64, 256>>>(node, pl0w, pl0b, l1);
    prep_wsplit_kernel<<<1004, 256>>>(f1w, f2w);
    e3_main_kernel<<<NE / 64, THREADS, SM_TOTAL>>>(pair, pidx, esh, esrc, edst,
                                                   lng, lnb, f1b, f2b);
    finalize_kernel<<<NNODE, 256>>>(node, l1, pnw, pnb, out);
}